// round 16
// baseline (speedup 1.0000x reference)
#include <cuda_runtime.h>
#include <cuda_fp16.h>
#include <cstdint>
#include <math.h>

#define NQ    16384
#define NM    16384
#define DIM   128
#define KNN   5
#define TILES 128
#define MSPLIT 2
#define NSLICE (MSPLIT * 4)          // stripe lists per query
#define TPC   (TILES / MSPLIT)       // 64 tiles per CTA
#define QB    64                     // queries per CTA
#define CHUNK_BYTES 16384            // 128 m-rows x 128 B (64 fp16 K-cols)
#define TILE_BYTES  32768            // 2 chunks (K=128)
#define NSTEP (2 * TPC)              // chunk steps per CTA

#define AS_OFF   0                   // 16 KB resident A (fp16 -2q), 64 rows
#define A_CHUNK  8192
#define BS_OFF   16384               // 3 x 16 KB B ring
#define DIST_OFF 65536               // 128 x 66 x 4 = 33792
#define PITCH    66
#define SMEM_TOTAL (DIST_OFF + 128 * PITCH * 4)   // 99328

#define FLT_BIG 3.402823466e+38f

__device__ __align__(128) unsigned char g_B[(size_t)TILES * TILE_BYTES];  // 4 MB
__device__ float g_m2[NM];
__device__ int   g_ci[NQ][NSLICE][KNN];

// ---------------------------------------------------------------------------
__device__ __forceinline__ uint32_t smem_u32(const void* p) {
    uint32_t a;
    asm("{ .reg .u64 t; cvta.to.shared.u64 t, %1; cvt.u32.u64 %0, t; }" : "=r"(a) : "l"(p));
    return a;
}

// B global blocks: [2 chunks][128 rows][128B], xor swizzle
__device__ __forceinline__ uint32_t goff(int r, int k) {
    int kc = k >> 6, kl = k & 63;
    return (uint32_t)(kc * CHUNK_BYTES + r * 128 + ((((kl >> 3) ^ (r & 7))) << 4) + ((kl & 7) << 1));
}
// A smem: [2 chunks][64 rows][128B], xor swizzle
__device__ __forceinline__ uint32_t aoff(int r, int k) {
    int kc = k >> 6, kl = k & 63;
    return (uint32_t)(kc * A_CHUNK + r * 128 + ((((kl >> 3) ^ (r & 7))) << 4) + ((kl & 7) << 1));
}

__device__ __forceinline__ uint32_t pack2f16(float a, float b) {
    __half2 h = __floats2half2_rn(a, b);
    return *reinterpret_cast<uint32_t*>(&h);
}

__device__ __forceinline__ void cpa16(uint32_t dst, const void* src) {
    asm volatile("cp.async.cg.shared.global [%0], [%1], 16;" :: "r"(dst), "l"(src));
}

#define LDSM_X4(r0, r1, r2, r3, addr) \
    asm volatile("ldmatrix.sync.aligned.m8n8.x4.shared.b16 {%0,%1,%2,%3}, [%4];" \
        : "=r"(r0), "=r"(r1), "=r"(r2), "=r"(r3) : "r"(addr))

// fp16 inputs, fp32 accumulate
#define MMA16816(d, a, b0, b1) \
    asm volatile("mma.sync.aligned.m16n8k16.row.col.f32.f16.f16.f32 " \
        "{%0,%1,%2,%3}, {%4,%5,%6,%7}, {%8,%9}, {%0,%1,%2,%3};" \
        : "+f"((d)[0]), "+f"((d)[1]), "+f"((d)[2]), "+f"((d)[3]) \
        : "r"((a)[0]), "r"((a)[1]), "r"((a)[2]), "r"((a)[3]), "r"(b0), "r"(b1))

#define INSERT5(bst, bix, val, idx) do { \
    if ((val) < (bst)[KNN - 1]) { \
        (bst)[KNN - 1] = (val); (bix)[KNN - 1] = (idx); \
        _Pragma("unroll") \
        for (int _s = KNN - 1; _s > 0; --_s) { \
            if ((bst)[_s] < (bst)[_s - 1]) { \
                float _tf = (bst)[_s]; (bst)[_s] = (bst)[_s - 1]; (bst)[_s - 1] = _tf; \
                int   _ti = (bix)[_s]; (bix)[_s] = (bix)[_s - 1]; (bix)[_s - 1] = _ti; \
            } \
        } \
    } } while (0)

// ---------------------------------------------------------------------------
// Prepass: memory bank -> swizzled fp16 blocks + m2
// ---------------------------------------------------------------------------
__global__ void __launch_bounds__(256)
prepass_kernel(const float* __restrict__ mbank) {
    int i = blockIdx.x * 256 + threadIdx.x;
    int t = i >> 7, r = i & 127;
    unsigned char* blk = g_B + (size_t)t * TILE_BYTES;
    const float4* row = reinterpret_cast<const float4*>(mbank + (size_t)i * DIM);
    float m2 = 0.f;
#pragma unroll
    for (int j = 0; j < 32; ++j) {
        float4 v = row[j];
        m2 = fmaf(v.x, v.x, m2); m2 = fmaf(v.y, v.y, m2);
        m2 = fmaf(v.z, v.z, m2); m2 = fmaf(v.w, v.w, m2);
        int d0 = j * 4;
        *(uint32_t*)(blk + goff(r, d0))     = pack2f16(v.x, v.y);
        *(uint32_t*)(blk + goff(r, d0 + 2)) = pack2f16(v.z, v.w);
    }
    g_m2[i] = m2;
}

// ---------------------------------------------------------------------------
// Main: grid (256 qtiles, 2 mslices); 256 thr; 64 q x 8192 m; occ 2
// fp16-input / fp32-accumulate HMMA; stripe top-5 export (no merge)
// ---------------------------------------------------------------------------
__global__ void __launch_bounds__(256, 2)
knn_main(const float* __restrict__ query) {
    extern __shared__ char smem[];
    const uint32_t sb = smem_u32(smem);
    const int tid  = threadIdx.x;
    const int lane = tid & 31;
    const int wid  = tid >> 5;          // 0..7
    const int wq   = wid >> 2;          // 0..1 : 32-q slice
    const int wx   = wid & 3;           // 0..3 : 32-m slice
    const int qbase  = blockIdx.x * QB;
    const int mslice = blockIdx.y;
    const int tile0  = mslice * TPC;
    const unsigned char* gsrc = g_B + (size_t)tile0 * TILE_BYTES;

    // preamble: load chunks 0,1 into ring slots 0,1 (16KB / 256 thr = 4 x 16B)
#pragma unroll
    for (int c = 0; c < 2; ++c) {
        uint32_t dst = sb + BS_OFF + (uint32_t)c * CHUNK_BYTES;
        const unsigned char* src = gsrc + (size_t)c * CHUNK_BYTES;
#pragma unroll
        for (int p = 0; p < 4; ++p)
            cpa16(dst + p * 4096 + tid * 16, src + p * 4096 + tid * 16);
        asm volatile("cp.async.commit_group;" ::: "memory");
    }

    // A = fp16(-2q), 64 rows, quarter-row per thread
    {
        int row  = tid >> 2;
        int part = tid & 3;
        const float4* r4 = reinterpret_cast<const float4*>(query + (size_t)(qbase + row) * DIM) + part * 8;
#pragma unroll
        for (int j = 0; j < 8; ++j) {
            float4 v = r4[j];
            int d0 = (part * 8 + j) * 4;
            *(uint32_t*)(smem + AS_OFF + aoff(row, d0))     = pack2f16(-2.f * v.x, -2.f * v.y);
            *(uint32_t*)(smem + AS_OFF + aoff(row, d0 + 2)) = pack2f16(-2.f * v.z, -2.f * v.w);
        }
    }

    const int r_l = lane & 15;
    const int cb  = lane >> 4;
    uint32_t abase[2]; int axor[2];
#pragma unroll
    for (int mi = 0; mi < 2; ++mi) {
        int row = wq * 32 + mi * 16 + r_l;
        abase[mi] = sb + AS_OFF + (uint32_t)row * 128;
        axor[mi]  = row & 7;
    }
    uint32_t bbase[2]; int bxor[2];
#pragma unroll
    for (int nh = 0; nh < 2; ++nh) {
        int row = wx * 32 + nh * 16 + r_l;
        bbase[nh] = sb + BS_OFF + (uint32_t)row * 128;
        bxor[nh]  = row & 7;
    }

    const int g0  = lane >> 2;
    const int cp2 = (lane & 3) * 2;

    float* Dist = reinterpret_cast<float*>(smem + DIST_OFF);
    const int scan_q = tid & 63;
    const int scan_h = tid >> 6;        // 0..3, 32 m each
    const float* scol = Dist + (size_t)(scan_h * 32) * PITCH + scan_q;

    float best[KNN]; int bidx[KNN];
#pragma unroll
    for (int s = 0; s < KNN; ++s) { best[s] = FLT_BIG; bidx[s] = 0; }

    int slot_cons = 0, slot_pref = 2;
    int prev_mb = -1;

    float acc[2][4][4];
    float m2c[4][2];

    for (int step = 0; step < NSTEP; ++step) {
        const int t  = step >> 1;
        const int kc = step & 1;

        asm volatile("cp.async.wait_group 1;" ::: "memory");
        __syncthreads();

        // prefetch chunk step+2 into slot_pref
        {
            int nn = step + 2;
            if (nn < NSTEP) {
                const unsigned char* src = gsrc + (size_t)nn * CHUNK_BYTES;
                uint32_t dst = sb + BS_OFF + (uint32_t)slot_pref * CHUNK_BYTES;
#pragma unroll
                for (int p = 0; p < 4; ++p)
                    cpa16(dst + p * 4096 + tid * 16, src + p * 4096 + tid * 16);
            }
            asm volatile("cp.async.commit_group;" ::: "memory");
        }

        if (kc == 0) {
            // scan previous tile's Dist (overlaps other warps' MMA)
            if (prev_mb >= 0) {
                const int ib = prev_mb + scan_h * 32;
#pragma unroll 4
                for (int j = 0; j < 32; ++j) {
                    float c = scol[j * PITCH];
                    INSERT5(best, bidx, c, ib + j);
                }
            }
            // zero accumulators, load m2 for this tile
#pragma unroll
            for (int mi = 0; mi < 2; ++mi)
#pragma unroll
                for (int ni = 0; ni < 4; ++ni)
#pragma unroll
                    for (int s = 0; s < 4; ++s) acc[mi][ni][s] = 0.f;
            int mb = (tile0 + t) * 128 + wx * 32 + cp2;
#pragma unroll
            for (int ni = 0; ni < 4; ++ni) {
                m2c[ni][0] = __ldg(&g_m2[mb + ni * 8]);
                m2c[ni][1] = __ldg(&g_m2[mb + ni * 8 + 1]);
            }
        }

        // 4 kt of MMA on this chunk
        const uint32_t bufoff = (uint32_t)slot_cons * CHUNK_BYTES;
        const uint32_t akco   = (uint32_t)kc * A_CHUNK;
#pragma unroll
        for (int kt = 0; kt < 4; ++kt) {
            uint32_t a[2][4];
#pragma unroll
            for (int mi = 0; mi < 2; ++mi) {
                uint32_t addr = abase[mi] + akco
                              + (uint32_t)((((kt * 2 + cb) ^ axor[mi])) << 4);
                LDSM_X4(a[mi][0], a[mi][1], a[mi][2], a[mi][3], addr);
            }
            uint32_t b[2][4];
#pragma unroll
            for (int nh = 0; nh < 2; ++nh) {
                uint32_t addr = bbase[nh] + bufoff
                              + (uint32_t)((((kt * 2 + cb) ^ bxor[nh])) << 4);
                LDSM_X4(b[nh][0], b[nh][1], b[nh][2], b[nh][3], addr);
            }
#pragma unroll
            for (int mi = 0; mi < 2; ++mi)
#pragma unroll
                for (int ni = 0; ni < 4; ++ni) {
                    int nh = ni >> 1, sub = ni & 1;
                    MMA16816(acc[mi][ni], a[mi], b[nh][sub], b[nh][sub + 2]);
                }
        }

        if (kc == 1) {
            // epilogue: m2 - 2 q.m into Dist[m][q]
            // c0/c1 -> q row q0; c2/c3 -> q row q0+8
#pragma unroll
            for (int mi = 0; mi < 2; ++mi) {
                int q0 = wq * 32 + mi * 16 + g0;
#pragma unroll
                for (int ni = 0; ni < 4; ++ni) {
                    int m0 = wx * 32 + ni * 8 + cp2;
                    Dist[m0 * PITCH + q0]           = acc[mi][ni][0] + m2c[ni][0];
                    Dist[(m0 + 1) * PITCH + q0]     = acc[mi][ni][1] + m2c[ni][1];
                    Dist[m0 * PITCH + q0 + 8]       = acc[mi][ni][2] + m2c[ni][0];
                    Dist[(m0 + 1) * PITCH + q0 + 8] = acc[mi][ni][3] + m2c[ni][1];
                }
            }
            prev_mb = (tile0 + t) * 128;
        }

        slot_cons = (slot_cons == 2) ? 0 : slot_cons + 1;
        slot_pref = (slot_pref == 2) ? 0 : slot_pref + 1;
    }

    // final tile's scan
    __syncthreads();
    {
        const int ib = prev_mb + scan_h * 32;
#pragma unroll 4
        for (int j = 0; j < 32; ++j) {
            float c = scol[j * PITCH];
            INSERT5(best, bidx, c, ib + j);
        }
    }

    // export stripe top-5 directly (no merge): slice index = mslice*4 + scan_h
    {
        int q = qbase + scan_q;
#pragma unroll
        for (int s = 0; s < KNN; ++s)
            g_ci[q][mslice * 4 + scan_h][s] = bidx[s];
    }
}

// ---------------------------------------------------------------------------
// Finalize: exact fp32 rescore of 40 candidates/query, top-5, output math
// ---------------------------------------------------------------------------
__global__ void __launch_bounds__(128)
finalize_kernel(const float* __restrict__ query,
                const float* __restrict__ mbank,
                const float* __restrict__ scale,
                float* __restrict__ out) {
    int q = blockIdx.x * 128 + threadIdx.x;
    const float4* q4 = reinterpret_cast<const float4*>(query + (size_t)q * DIM);

    float best[KNN]; int bidx[KNN];
#pragma unroll
    for (int s = 0; s < KNN; ++s) { best[s] = FLT_BIG; bidx[s] = 0; }

    for (int sl = 0; sl < NSLICE; ++sl) {
#pragma unroll
        for (int s = 0; s < KNN; ++s) {
            int idx = g_ci[q][sl][s];
            const float4* m4 = reinterpret_cast<const float4*>(mbank + (size_t)idx * DIM);
            float s0 = 0.f, s1 = 0.f, s2 = 0.f, s3 = 0.f;
#pragma unroll
            for (int j = 0; j < 32; ++j) {
                float4 a = q4[j], b = m4[j];
                float dx = a.x - b.x, dy = a.y - b.y, dz = a.z - b.z, dw = a.w - b.w;
                s0 = fmaf(dx, dx, s0); s1 = fmaf(dy, dy, s1);
                s2 = fmaf(dz, dz, s2); s3 = fmaf(dw, dw, s3);
            }
            float d2 = (s0 + s1) + (s2 + s3);
            INSERT5(best, bidx, d2, idx);
        }
    }

    float d[KNN];
#pragma unroll
    for (int s = 0; s < KNN; ++s)
        d[s] = sqrtf(fmaxf(best[s], 1e-12f));

    float W = 0.f, wd = 0.f;
#pragma unroll
    for (int s = 0; s < KNN; ++s) {
        float e = expf(d[0] - d[s]);
        W += e; wd += e * d[s];
    }
    wd /= W;

    float ns = 0.f;
#pragma unroll
    for (int s = 0; s < KNN; ++s) ns += scale[bidx[s]];
    ns *= (1.f / KNN);
    float nd = wd / fmaxf(ns, 1e-6f);

    float mean = 0.f;
#pragma unroll
    for (int s = 0; s < KNN; ++s) mean += d[s];
    mean *= (1.f / KNN);
    float var = 0.f;
#pragma unroll
    for (int s = 0; s < KNN; ++s) { float u = d[s] - mean; var = fmaf(u, u, var); }
    var *= (1.f / KNN);
    float cons = sqrtf(fmaxf(var, 0.f)) / fmaxf(mean, 1e-6f);

    out[q] = nd * (1.f + 0.5f * cons);
}

// ---------------------------------------------------------------------------
extern "C" void kernel_launch(void* const* d_in, const int* in_sizes, int n_in,
                              void* d_out, int out_size) {
    const float* query = (const float*)d_in[0];
    const float* mbank = (const float*)d_in[1];
    const float* scale = (const float*)d_in[2];
    float* out = (float*)d_out;
    (void)in_sizes; (void)n_in; (void)out_size;

    cudaFuncSetAttribute(knn_main, cudaFuncAttributeMaxDynamicSharedMemorySize, SMEM_TOTAL);

    prepass_kernel<<<NM / 256, 256>>>(mbank);
    dim3 grid(NQ / QB, MSPLIT);
    knn_main<<<grid, 256, SMEM_TOTAL>>>(query);
    finalize_kernel<<<NQ / 128, 128>>>(query, mbank, scale, out);
}

// round 17
// speedup vs baseline: 1.1217x; 1.1217x over previous
#include <cuda_runtime.h>
#include <cuda_fp16.h>
#include <cstdint>
#include <math.h>

#define NQ    16384
#define NM    16384
#define DIM   128
#define KNN   5
#define TILES 128
#define MSPLIT 4
#define NSLICE (MSPLIT * 4)          // 16 stripe lists per query
#define TOPR  10                     // rescore pool size
#define TPC   (TILES / MSPLIT)       // 32 tiles per CTA
#define QB    64                     // queries per CTA
#define CHUNK_BYTES 16384            // 128 m-rows x 128 B (64 fp16 K-cols)
#define TILE_BYTES  32768            // 2 chunks (K=128)
#define NSTEP (2 * TPC)              // chunk steps per CTA

#define AS_OFF   0                   // 16 KB resident A (fp16 -2q), 64 rows
#define A_CHUNK  8192
#define BS_OFF   16384               // 3 x 16 KB B ring
#define DIST_OFF 65536               // 128 x 66 x 4 = 33792
#define PITCH    66
#define SMEM_TOTAL (DIST_OFF + 128 * PITCH * 4)   // 99328

#define FLT_BIG 3.402823466e+38f

__device__ __align__(128) unsigned char g_B[(size_t)TILES * TILE_BYTES];  // 4 MB
__device__ float g_m2[NM];
__device__ float g_cd[NQ][NSLICE][KNN];
__device__ int   g_ci[NQ][NSLICE][KNN];

// ---------------------------------------------------------------------------
__device__ __forceinline__ uint32_t smem_u32(const void* p) {
    uint32_t a;
    asm("{ .reg .u64 t; cvta.to.shared.u64 t, %1; cvt.u32.u64 %0, t; }" : "=r"(a) : "l"(p));
    return a;
}

// B global blocks: [2 chunks][128 rows][128B], xor swizzle
__device__ __forceinline__ uint32_t goff(int r, int k) {
    int kc = k >> 6, kl = k & 63;
    return (uint32_t)(kc * CHUNK_BYTES + r * 128 + ((((kl >> 3) ^ (r & 7))) << 4) + ((kl & 7) << 1));
}
// A smem: [2 chunks][64 rows][128B], xor swizzle
__device__ __forceinline__ uint32_t aoff(int r, int k) {
    int kc = k >> 6, kl = k & 63;
    return (uint32_t)(kc * A_CHUNK + r * 128 + ((((kl >> 3) ^ (r & 7))) << 4) + ((kl & 7) << 1));
}

__device__ __forceinline__ uint32_t pack2f16(float a, float b) {
    __half2 h = __floats2half2_rn(a, b);
    return *reinterpret_cast<uint32_t*>(&h);
}

__device__ __forceinline__ void cpa16(uint32_t dst, const void* src) {
    asm volatile("cp.async.cg.shared.global [%0], [%1], 16;" :: "r"(dst), "l"(src));
}

#define LDSM_X4(r0, r1, r2, r3, addr) \
    asm volatile("ldmatrix.sync.aligned.m8n8.x4.shared.b16 {%0,%1,%2,%3}, [%4];" \
        : "=r"(r0), "=r"(r1), "=r"(r2), "=r"(r3) : "r"(addr))

// f16 accumulate: D,C are 2 x b32 (half2 pairs)
#define MMA16816H(d, a, b0, b1) \
    asm volatile("mma.sync.aligned.m16n8k16.row.col.f16.f16.f16.f16 " \
        "{%0,%1}, {%2,%3,%4,%5}, {%6,%7}, {%0,%1};" \
        : "+r"((d)[0]), "+r"((d)[1]) \
        : "r"((a)[0]), "r"((a)[1]), "r"((a)[2]), "r"((a)[3]), "r"(b0), "r"(b1))

#define INSERTN(N, bst, bix, val, idx) do { \
    if ((val) < (bst)[(N) - 1]) { \
        (bst)[(N) - 1] = (val); (bix)[(N) - 1] = (idx); \
        _Pragma("unroll") \
        for (int _s = (N) - 1; _s > 0; --_s) { \
            if ((bst)[_s] < (bst)[_s - 1]) { \
                float _tf = (bst)[_s]; (bst)[_s] = (bst)[_s - 1]; (bst)[_s - 1] = _tf; \
                int   _ti = (bix)[_s]; (bix)[_s] = (bix)[_s - 1]; (bix)[_s - 1] = _ti; \
            } \
        } \
    } } while (0)

#define INSERT5(bst, bix, val, idx) INSERTN(KNN, bst, bix, val, idx)

// ---------------------------------------------------------------------------
// Prepass: memory bank -> swizzled fp16 blocks + m2
// ---------------------------------------------------------------------------
__global__ void __launch_bounds__(256)
prepass_kernel(const float* __restrict__ mbank) {
    int i = blockIdx.x * 256 + threadIdx.x;
    int t = i >> 7, r = i & 127;
    unsigned char* blk = g_B + (size_t)t * TILE_BYTES;
    const float4* row = reinterpret_cast<const float4*>(mbank + (size_t)i * DIM);
    float m2 = 0.f;
#pragma unroll
    for (int j = 0; j < 32; ++j) {
        float4 v = row[j];
        m2 = fmaf(v.x, v.x, m2); m2 = fmaf(v.y, v.y, m2);
        m2 = fmaf(v.z, v.z, m2); m2 = fmaf(v.w, v.w, m2);
        int d0 = j * 4;
        *(uint32_t*)(blk + goff(r, d0))     = pack2f16(v.x, v.y);
        *(uint32_t*)(blk + goff(r, d0 + 2)) = pack2f16(v.z, v.w);
    }
    g_m2[i] = m2;
}

// ---------------------------------------------------------------------------
// Main: grid (256 qtiles, 4 mslices); 256 thr; 64 q x 4096 m; occ 2
// f16-accumulate HMMA; stripe top-5 export with values (no merge)
// ---------------------------------------------------------------------------
__global__ void __launch_bounds__(256, 2)
knn_main(const float* __restrict__ query) {
    extern __shared__ char smem[];
    const uint32_t sb = smem_u32(smem);
    const int tid  = threadIdx.x;
    const int lane = tid & 31;
    const int wid  = tid >> 5;          // 0..7
    const int wq   = wid >> 2;          // 0..1 : 32-q slice
    const int wx   = wid & 3;           // 0..3 : 32-m slice
    const int qbase  = blockIdx.x * QB;
    const int mslice = blockIdx.y;
    const int tile0  = mslice * TPC;
    const unsigned char* gsrc = g_B + (size_t)tile0 * TILE_BYTES;

    // preamble: load chunks 0,1 into ring slots 0,1 (16KB / 256 thr = 4 x 16B)
#pragma unroll
    for (int c = 0; c < 2; ++c) {
        uint32_t dst = sb + BS_OFF + (uint32_t)c * CHUNK_BYTES;
        const unsigned char* src = gsrc + (size_t)c * CHUNK_BYTES;
#pragma unroll
        for (int p = 0; p < 4; ++p)
            cpa16(dst + p * 4096 + tid * 16, src + p * 4096 + tid * 16);
        asm volatile("cp.async.commit_group;" ::: "memory");
    }

    // A = fp16(-2q), 64 rows, quarter-row per thread
    {
        int row  = tid >> 2;
        int part = tid & 3;
        const float4* r4 = reinterpret_cast<const float4*>(query + (size_t)(qbase + row) * DIM) + part * 8;
#pragma unroll
        for (int j = 0; j < 8; ++j) {
            float4 v = r4[j];
            int d0 = (part * 8 + j) * 4;
            *(uint32_t*)(smem + AS_OFF + aoff(row, d0))     = pack2f16(-2.f * v.x, -2.f * v.y);
            *(uint32_t*)(smem + AS_OFF + aoff(row, d0 + 2)) = pack2f16(-2.f * v.z, -2.f * v.w);
        }
    }

    const int r_l = lane & 15;
    const int cb  = lane >> 4;
    uint32_t abase[2]; int axor[2];
#pragma unroll
    for (int mi = 0; mi < 2; ++mi) {
        int row = wq * 32 + mi * 16 + r_l;
        abase[mi] = sb + AS_OFF + (uint32_t)row * 128;
        axor[mi]  = row & 7;
    }
    uint32_t bbase[2]; int bxor[2];
#pragma unroll
    for (int nh = 0; nh < 2; ++nh) {
        int row = wx * 32 + nh * 16 + r_l;
        bbase[nh] = sb + BS_OFF + (uint32_t)row * 128;
        bxor[nh]  = row & 7;
    }

    const int g0  = lane >> 2;
    const int cp2 = (lane & 3) * 2;

    float* Dist = reinterpret_cast<float*>(smem + DIST_OFF);
    const int scan_q = tid & 63;
    const int scan_h = tid >> 6;        // 0..3, 32 m each
    const float* scol = Dist + (size_t)(scan_h * 32) * PITCH + scan_q;

    float best[KNN]; int bidx[KNN];
#pragma unroll
    for (int s = 0; s < KNN; ++s) { best[s] = FLT_BIG; bidx[s] = 0; }

    int slot_cons = 0, slot_pref = 2;
    int prev_mb = -1;

    uint32_t acc[2][4][2];              // half2 accumulators
    float m2c[4][2];

    for (int step = 0; step < NSTEP; ++step) {
        const int t  = step >> 1;
        const int kc = step & 1;

        asm volatile("cp.async.wait_group 1;" ::: "memory");
        __syncthreads();

        // prefetch chunk step+2 into slot_pref
        {
            int nn = step + 2;
            if (nn < NSTEP) {
                const unsigned char* src = gsrc + (size_t)nn * CHUNK_BYTES;
                uint32_t dst = sb + BS_OFF + (uint32_t)slot_pref * CHUNK_BYTES;
#pragma unroll
                for (int p = 0; p < 4; ++p)
                    cpa16(dst + p * 4096 + tid * 16, src + p * 4096 + tid * 16);
            }
            asm volatile("cp.async.commit_group;" ::: "memory");
        }

        if (kc == 0) {
            // scan previous tile's Dist (overlaps other warps' MMA)
            if (prev_mb >= 0) {
                const int ib = prev_mb + scan_h * 32;
#pragma unroll 4
                for (int j = 0; j < 32; ++j) {
                    float c = scol[j * PITCH];
                    INSERT5(best, bidx, c, ib + j);
                }
            }
            // zero accumulators, load m2 for this tile
#pragma unroll
            for (int mi = 0; mi < 2; ++mi)
#pragma unroll
                for (int ni = 0; ni < 4; ++ni) {
                    acc[mi][ni][0] = 0u; acc[mi][ni][1] = 0u;
                }
            int mb = (tile0 + t) * 128 + wx * 32 + cp2;
#pragma unroll
            for (int ni = 0; ni < 4; ++ni) {
                m2c[ni][0] = __ldg(&g_m2[mb + ni * 8]);
                m2c[ni][1] = __ldg(&g_m2[mb + ni * 8 + 1]);
            }
        }

        // 4 kt of MMA on this chunk
        const uint32_t bufoff = (uint32_t)slot_cons * CHUNK_BYTES;
        const uint32_t akco   = (uint32_t)kc * A_CHUNK;
#pragma unroll
        for (int kt = 0; kt < 4; ++kt) {
            uint32_t a[2][4];
#pragma unroll
            for (int mi = 0; mi < 2; ++mi) {
                uint32_t addr = abase[mi] + akco
                              + (uint32_t)((((kt * 2 + cb) ^ axor[mi])) << 4);
                LDSM_X4(a[mi][0], a[mi][1], a[mi][2], a[mi][3], addr);
            }
            uint32_t b[2][4];
#pragma unroll
            for (int nh = 0; nh < 2; ++nh) {
                uint32_t addr = bbase[nh] + bufoff
                              + (uint32_t)((((kt * 2 + cb) ^ bxor[nh])) << 4);
                LDSM_X4(b[nh][0], b[nh][1], b[nh][2], b[nh][3], addr);
            }
#pragma unroll
            for (int mi = 0; mi < 2; ++mi)
#pragma unroll
                for (int ni = 0; ni < 4; ++ni) {
                    int nh = ni >> 1, sub = ni & 1;
                    MMA16816H(acc[mi][ni], a[mi], b[nh][sub], b[nh][sub + 2]);
                }
        }

        if (kc == 1) {
            // epilogue: m2 + dot(f16->f32) into Dist[m][q]
            // reg0 = {c0,c1} -> q row q0; reg1 = {c2,c3} -> q row q0+8
#pragma unroll
            for (int mi = 0; mi < 2; ++mi) {
                int q0 = wq * 32 + mi * 16 + g0;
#pragma unroll
                for (int ni = 0; ni < 4; ++ni) {
                    int m0 = wx * 32 + ni * 8 + cp2;
                    float2 lo = __half22float2(*reinterpret_cast<__half2*>(&acc[mi][ni][0]));
                    float2 hi = __half22float2(*reinterpret_cast<__half2*>(&acc[mi][ni][1]));
                    Dist[m0 * PITCH + q0]           = lo.x + m2c[ni][0];
                    Dist[(m0 + 1) * PITCH + q0]     = lo.y + m2c[ni][1];
                    Dist[m0 * PITCH + q0 + 8]       = hi.x + m2c[ni][0];
                    Dist[(m0 + 1) * PITCH + q0 + 8] = hi.y + m2c[ni][1];
                }
            }
            prev_mb = (tile0 + t) * 128;
        }

        slot_cons = (slot_cons == 2) ? 0 : slot_cons + 1;
        slot_pref = (slot_pref == 2) ? 0 : slot_pref + 1;
    }

    // final tile's scan
    __syncthreads();
    {
        const int ib = prev_mb + scan_h * 32;
#pragma unroll 4
        for (int j = 0; j < 32; ++j) {
            float c = scol[j * PITCH];
            INSERT5(best, bidx, c, ib + j);
        }
    }

    // export stripe top-5 with estimated values (no merge)
    {
        int q  = qbase + scan_q;
        int sl = mslice * 4 + scan_h;
#pragma unroll
        for (int s = 0; s < KNN; ++s) {
            g_cd[q][sl][s] = best[s];
            g_ci[q][sl][s] = bidx[s];
        }
    }
}

// ---------------------------------------------------------------------------
// Finalize: merge 80 estimates -> top-10 -> exact fp32 rescore -> top-5
// ---------------------------------------------------------------------------
__global__ void __launch_bounds__(128)
finalize_kernel(const float* __restrict__ query,
                const float* __restrict__ mbank,
                const float* __restrict__ scale,
                float* __restrict__ out) {
    int q = blockIdx.x * 128 + threadIdx.x;
    const float4* q4 = reinterpret_cast<const float4*>(query + (size_t)q * DIM);

    // top-TOPR by estimated value
    float ev[TOPR]; int ei[TOPR];
#pragma unroll
    for (int r = 0; r < TOPR; ++r) { ev[r] = FLT_BIG; ei[r] = 0; }
    for (int sl = 0; sl < NSLICE; ++sl) {
#pragma unroll
        for (int s = 0; s < KNN; ++s)
            INSERTN(TOPR, ev, ei, g_cd[q][sl][s], g_ci[q][sl][s]);
    }

    // exact fp32 rescore of the TOPR pool
    float best[KNN]; int bidx[KNN];
#pragma unroll
    for (int s = 0; s < KNN; ++s) { best[s] = FLT_BIG; bidx[s] = 0; }
#pragma unroll
    for (int r = 0; r < TOPR; ++r) {
        int idx = ei[r];
        const float4* m4 = reinterpret_cast<const float4*>(mbank + (size_t)idx * DIM);
        float s0 = 0.f, s1 = 0.f, s2 = 0.f, s3 = 0.f;
#pragma unroll
        for (int j = 0; j < 32; ++j) {
            float4 a = q4[j], b = m4[j];
            float dx = a.x - b.x, dy = a.y - b.y, dz = a.z - b.z, dw = a.w - b.w;
            s0 = fmaf(dx, dx, s0); s1 = fmaf(dy, dy, s1);
            s2 = fmaf(dz, dz, s2); s3 = fmaf(dw, dw, s3);
        }
        float d2 = (s0 + s1) + (s2 + s3);
        INSERT5(best, bidx, d2, idx);
    }

    float d[KNN];
#pragma unroll
    for (int s = 0; s < KNN; ++s)
        d[s] = sqrtf(fmaxf(best[s], 1e-12f));

    float W = 0.f, wd = 0.f;
#pragma unroll
    for (int s = 0; s < KNN; ++s) {
        float e = expf(d[0] - d[s]);
        W += e; wd += e * d[s];
    }
    wd /= W;

    float ns = 0.f;
#pragma unroll
    for (int s = 0; s < KNN; ++s) ns += scale[bidx[s]];
    ns *= (1.f / KNN);
    float nd = wd / fmaxf(ns, 1e-6f);

    float mean = 0.f;
#pragma unroll
    for (int s = 0; s < KNN; ++s) mean += d[s];
    mean *= (1.f / KNN);
    float var = 0.f;
#pragma unroll
    for (int s = 0; s < KNN; ++s) { float u = d[s] - mean; var = fmaf(u, u, var); }
    var *= (1.f / KNN);
    float cons = sqrtf(fmaxf(var, 0.f)) / fmaxf(mean, 1e-6f);

    out[q] = nd * (1.f + 0.5f * cons);
}

// ---------------------------------------------------------------------------
extern "C" void kernel_launch(void* const* d_in, const int* in_sizes, int n_in,
                              void* d_out, int out_size) {
    const float* query = (const float*)d_in[0];
    const float* mbank = (const float*)d_in[1];
    const float* scale = (const float*)d_in[2];
    float* out = (float*)d_out;
    (void)in_sizes; (void)n_in; (void)out_size;

    cudaFuncSetAttribute(knn_main, cudaFuncAttributeMaxDynamicSharedMemorySize, SMEM_TOTAL);

    prepass_kernel<<<NM / 256, 256>>>(mbank);
    dim3 grid(NQ / QB, MSPLIT);
    knn_main<<<grid, 256, SMEM_TOTAL>>>(query);
    finalize_kernel<<<NQ / 128, 128>>>(query, mbank, scale, out);
}